// round 16
// baseline (speedup 1.0000x reference)
#include <cuda_runtime.h>
#include <cuda_fp16.h>
#include <cstdint>

// Problem constants
#define BB  32
#define TT  256
#define DD  512
#define MPP 20

constexpr int TM     = 64;             // CTA t rows
constexpr int TN     = 32;             // s cols per verified chunk
constexpr int NCHK   = TT / TN;        // 8 s-chunks
constexpr int NM     = 5;              // m-planes per CTA (20 = 4 groups of 5)
constexpr int KC     = 64;             // k per pipeline stage (4 x k16)
constexpr int NST    = DD / KC;        // 8 stages
constexpr int STAGES = 2;              // buffer ring depth (produce-ahead 1)
constexpr int NTHR   = 128;            // 4 warps -> one per SMSP
constexpr int OCC    = 5;              // target CTAs/SM (102-reg cap, 20 warps/SM)
constexpr int ROWB   = 144;            // smem row bytes: 128B data + 16B pad
constexpr int A_BYTES   = TM * ROWB;              // 9216
constexpr int B_BYTES   = TN * ROWB;              // 4608
constexpr int STG_BYTES = A_BYTES + B_BYTES;      // 13824

constexpr int S_KMS  = 0;              // 5*512 halves = 5120 B
constexpr int S_MBAR = 5120;           // 4 x 8B mbarriers (2 full + 2 empty)
constexpr int S_BUF  = 5248;           // 128B aligned
constexpr int S_TOTAL = S_BUF + STAGES * STG_BYTES;  // 32896 B (x5 CTAs = 164KB)

constexpr float THRESH = 10.0f;        // tanh(10) = 1 - 4.1e-9; monotone-safe exit

// static device scratch (allocation-free per harness rules)
__device__ __half g_lt[BB * TT * DD];
__device__ __half g_rt0[BB * TN * DD];   // only s-chunk 0 of rt, pre-converted

static __device__ __forceinline__ uint32_t s2u(const void* p) {
    return (uint32_t)__cvta_generic_to_shared(p);
}

#define CP16(dst, src) \
    asm volatile("cp.async.cg.shared.global [%0], [%1], 16;" :: "r"(dst), "l"(src))

#define LDSM4(r0, r1, r2, r3, addr)                                              \
    asm volatile("ldmatrix.sync.aligned.m8n8.x4.shared.b16 {%0,%1,%2,%3}, [%4];" \
                 : "=r"(r0), "=r"(r1), "=r"(r2), "=r"(r3) : "r"(addr))

#define MMA16816(d0, d1, a0, a1, a2, a3, b0, b1)                                  \
    asm volatile("mma.sync.aligned.m16n8k16.row.col.f16.f16.f16.f16 "             \
                 "{%0,%1},{%2,%3,%4,%5},{%6,%7},{%0,%1};"                         \
                 : "+r"(d0), "+r"(d1)                                             \
                 : "r"(a0), "r"(a1), "r"(a2), "r"(a3), "r"(b0), "r"(b1))

// spin (with suspend hint) until the mbarrier phase with given parity completes
#define MBWAIT(addr, ph)                                                          \
    asm volatile("{\n\t.reg .pred P;\n\t"                                         \
                 "MBW%=:\n\t"                                                     \
                 "mbarrier.try_wait.parity.shared.b64 P, [%0], %1, 0x989680;\n\t" \
                 "@!P bra MBW%=;\n\t}"                                            \
                 :: "r"(addr), "r"(ph) : "memory")

static __device__ __forceinline__ uint32_t hmul2u(uint32_t a, uint32_t b) {
    __half2 r = __hmul2(*reinterpret_cast<__half2*>(&a),
                        *reinterpret_cast<__half2*>(&b));
    return *reinterpret_cast<uint32_t*>(&r);
}
static __device__ __forceinline__ uint32_t f2h2(float lo, float hi) {
    __half2 h = __floats2half2_rn(lo, hi);
    return *reinterpret_cast<uint32_t*>(&h);
}

// ---------------------------------------------------------------------------
// Kernel 1: convert lt (all) + rt s-chunk-0 rows to fp16.
// ---------------------------------------------------------------------------
constexpr int NLT  = BB * TT * DD / 16;   // 262144
constexpr int NRT0 = BB * TN * DD / 16;   // 32768
constexpr int NCVT = NLT + NRT0;          // 294912

__global__ void cvt_kernel(const float* __restrict__ lt, const float* __restrict__ rt) {
    int i = blockIdx.x * blockDim.x + threadIdx.x;
    const float4* src;
    __half* dst;
    if (i < NLT) {
        src = reinterpret_cast<const float4*>(lt) + (size_t)i * 4;
        dst = g_lt + (size_t)i * 16;
    } else {
        int j = i - NLT;                       // unit within rt chunk-0 view
        int per_b = TN * DD / 16;              // 1024 units per b
        int b = j / per_b, r = j % per_b;      // rows 0..31 contiguous per b
        src = reinterpret_cast<const float4*>(rt + (size_t)b * TT * DD) + (size_t)r * 4;
        dst = g_rt0 + ((size_t)b * TN * DD + (size_t)r * 16);
    }
    float4 a[4];
#pragma unroll
    for (int j = 0; j < 4; j++) a[j] = src[j];
    uint32_t w[8];
#pragma unroll
    for (int j = 0; j < 4; j++) {
        w[j * 2]     = f2h2(a[j].x, a[j].y);
        w[j * 2 + 1] = f2h2(a[j].z, a[j].w);
    }
    uint4* d = reinterpret_cast<uint4*>(dst);
    d[0] = make_uint4(w[0], w[1], w[2], w[3]);
    d[1] = make_uint4(w[4], w[5], w[6], w[7]);
}

// ---------------------------------------------------------------------------
// Kernel 2: one CTA = (b, t-tile 64, 5 m-planes), 128 threads, 5 CTAs/SM
// (102-reg cap -> 20 warps/SM for latency hiding). s-chunk 0 via mbarrier
// cp.async pipeline (ring 2); monotone-safe early exit; rare exact fallback
// over chunks 1..7 (B converted from f32 rt in-kernel, identical rounding).
// fp16 HMMA fp16-acc, km folded in registers, LDSM fragment path.
// ---------------------------------------------------------------------------
__global__ __launch_bounds__(NTHR, OCC)
void match_kernel(const float* __restrict__ kw, const float* __restrict__ rtf,
                  float* __restrict__ out) {
    extern __shared__ __align__(128) char smem[];
    const int tid = threadIdx.x;
    const int b   = blockIdx.z;
    const int m0  = blockIdx.y * NM;
    const int t0  = blockIdx.x * TM;
    const uint32_t sbase   = s2u(smem);
    const uint32_t sbuf    = sbase + S_BUF;
    const uint32_t mbfull  = sbase + S_MBAR;        // 2 x 8B
    const uint32_t mbempty = sbase + S_MBAR + 16;   // 2 x 8B

    if (tid == 0) {
#pragma unroll
        for (int i = 0; i < STAGES; i++) {
            asm volatile("mbarrier.init.shared.b64 [%0], %1;"
                         :: "r"(mbfull + 8 * i), "r"((uint32_t)NTHR) : "memory");
            asm volatile("mbarrier.init.shared.b64 [%0], %1;"
                         :: "r"(mbempty + 8 * i), "r"(4u) : "memory");
        }
    }

    // stage km rows (m0..m0+4) as fp16
    __half* kms = reinterpret_cast<__half*>(smem + S_KMS);
#pragma unroll
    for (int e = tid; e < NM * DD; e += NTHR) {
        int mi = e >> 9, c = e & (DD - 1);
        kms[e] = __float2half_rn(kw[(m0 + mi) * DD + c]);
    }
    __syncthreads();   // mbarrier init + kms visible

    const __half* ltb  = g_lt  + (size_t)(b * TT + t0) * DD;
    const __half* rt0b = g_rt0 + (size_t)b * TN * DD;
    const float*  rtfb = rtf   + (size_t)b * TT * DD;

    const int wid  = tid >> 5;    // warp = 16 t-rows (4 warps x 16 = 64)
    const int lane = tid & 31;
    const int wt   = wid;         // 0..3

    const uint32_t aoff = (uint32_t)(wt * 16 + (lane & 15)) * ROWB + (lane >> 4) * 16;
    const uint32_t boff = (uint32_t)((lane & 7) + ((lane >> 4) << 3)) * ROWB
                        + ((lane >> 3) & 1) * 16;
    const int c0 = (lane & 3) * 2;

    float runmax[NM][2];
#pragma unroll
    for (int mi = 0; mi < NM; mi++) { runmax[mi][0] = -3.4e38f; runmax[mi][1] = -3.4e38f; }

    int fullp[STAGES]  = {0, 0};
    int emptyp[STAGES] = {1, 1};

    auto issueA = [&](uint32_t sb, int st) {
        const int k0 = st * KC;
#pragma unroll
        for (int i = 0; i < 4; i++) {   // A: 64 rows x 8 x 16B = 512 chunks
            int c = tid + i * NTHR, row = c >> 3, sub = c & 7;
            CP16(sb + row * ROWB + sub * 16, ltb + row * DD + k0 + sub * 8);
        }
    };

    auto produce = [&](int st) {        // chunk-0 producer (B from g_rt0)
        const int bfi = st & 1;
        const uint32_t sb = sbuf + bfi * STG_BYTES;
        MBWAIT(mbempty + 8 * bfi, emptyp[bfi]);
        emptyp[bfi] ^= 1;
        issueA(sb, st);
#pragma unroll
        for (int i = 0; i < 2; i++) {   // B: 32 rows x 8 x 16B = 256 chunks
            int c = tid + i * NTHR, row = c >> 3, sub = c & 7;
            CP16(sb + A_BYTES + row * ROWB + sub * 16,
                 rt0b + row * DD + st * KC + sub * 8);
        }
        asm volatile("cp.async.mbarrier.arrive.noinc.shared.b64 [%0];"
                     :: "r"(mbfull + 8 * bfi) : "memory");
    };

    auto ldfrag = [&](uint32_t sb, int kk, uint32_t* bf, uint32_t* af) {
        LDSM4(bf[0], bf[1], bf[2], bf[3], sb + A_BYTES + boff + kk * 32);
        LDSM4(bf[4], bf[5], bf[6], bf[7], sb + A_BYTES + boff + 16 * ROWB + kk * 32);
        LDSM4(af[0], af[1], af[2], af[3], sb + aoff + kk * 32);
    };

    uint32_t acc[NM][4][2];
    auto clear_acc = [&]() {
#pragma unroll
        for (int mi = 0; mi < NM; mi++)
#pragma unroll
            for (int ni = 0; ni < 4; ni++) { acc[mi][ni][0] = 0u; acc[mi][ni][1] = 0u; }
    };

    auto compute = [&](uint32_t sb, int ki) {
        uint32_t bfA[8], afA[4], bfB[8], afB[4];
        ldfrag(sb, 0, bfA, afA);
#pragma unroll
        for (int kk = 0; kk < 4; kk++) {
            uint32_t* bf = (kk & 1) ? bfB : bfA;
            uint32_t* af = (kk & 1) ? afB : afA;
            if (kk < 3) ldfrag(sb, kk + 1, (kk & 1) ? bfA : bfB, (kk & 1) ? afA : afB);
            const int kb = ki * KC + kk * 16;
#pragma unroll
            for (int mi = 0; mi < NM; mi++) {
                const uint32_t kp0 =
                    *reinterpret_cast<const uint32_t*>(&kms[mi * DD + kb + c0]);
                const uint32_t kp1 =
                    *reinterpret_cast<const uint32_t*>(&kms[mi * DD + kb + c0 + 8]);
                uint32_t a0 = hmul2u(af[0], kp0);
                uint32_t a1 = hmul2u(af[1], kp0);
                uint32_t a2 = hmul2u(af[2], kp1);
                uint32_t a3 = hmul2u(af[3], kp1);
#pragma unroll
                for (int ni = 0; ni < 4; ni++)
                    MMA16816(acc[mi][ni][0], acc[mi][ni][1],
                             a0, a1, a2, a3, bf[ni * 2], bf[ni * 2 + 1]);
            }
        }
    };

    // returns true if every row's running max clears THRESH (monotone-safe)
    auto reduce_vote = [&]() -> int {
        bool pred = true;
#pragma unroll
        for (int mi = 0; mi < NM; mi++)
#pragma unroll
            for (int h = 0; h < 2; h++) {
                __half2 v = *reinterpret_cast<__half2*>(&acc[mi][0][h]);
#pragma unroll
                for (int ni = 1; ni < 4; ni++)
                    v = __hmax2(v, *reinterpret_cast<__half2*>(&acc[mi][ni][h]));
                float fm = fmaxf(__low2float(v), __high2float(v));
                fm = fmaxf(fm, __shfl_xor_sync(0xffffffffu, fm, 1));
                fm = fmaxf(fm, __shfl_xor_sync(0xffffffffu, fm, 2));
                runmax[mi][h] = fmaxf(runmax[mi][h], fm);
                pred = pred && (runmax[mi][h] > THRESH);
            }
        return __syncthreads_and((int)pred);
    };

    // ---- chunk 0: pipelined fast path (ring of 2, produce-ahead 1) ----
    clear_acc();
    produce(0);
#pragma unroll
    for (int ki = 0; ki < NST; ki++) {
        const int bfi = ki & 1;
        MBWAIT(mbfull + 8 * bfi, fullp[bfi]);
        fullp[bfi] ^= 1;
        if (ki + 1 < NST) produce(ki + 1);
        compute(sbuf + bfi * STG_BYTES, ki);
        __syncwarp();
        if (lane == 0) {
            asm volatile("{\n\t.reg .b64 t;\n\t"
                         "mbarrier.arrive.shared.b64 t, [%0];\n\t}"
                         :: "r"(mbempty + 8 * bfi) : "memory");
        }
    }
    int done = reduce_vote();

    // ---- chunks 1..7: rare exact fallback (B from f32 rt, converted here) ----
    if (!done) {
        for (int chunk = 1; chunk < NCHK; chunk++) {
            clear_acc();
            for (int ki = 0; ki < NST; ki++) {
                const uint32_t sb = sbuf + (ki & 1) * STG_BYTES;
                issueA(sb, ki);
                asm volatile("cp.async.commit_group;" ::: "memory");
#pragma unroll
                for (int i = 0; i < 2; i++) {   // B: f32 -> f16 in regs -> STS
                    int c = tid + i * NTHR, row = c >> 3, sub = c & 7;
                    const float* s = rtfb + (size_t)(chunk * TN + row) * DD
                                   + ki * KC + sub * 8;
                    float4 f0 = *reinterpret_cast<const float4*>(s);
                    float4 f1 = *reinterpret_cast<const float4*>(s + 4);
                    uint32_t w0 = f2h2(f0.x, f0.y), w1 = f2h2(f0.z, f0.w);
                    uint32_t w2 = f2h2(f1.x, f1.y), w3 = f2h2(f1.z, f1.w);
                    uint32_t dstp = sb + A_BYTES + row * ROWB + sub * 16;
                    asm volatile("st.shared.v4.b32 [%0], {%1,%2,%3,%4};"
                                 :: "r"(dstp), "r"(w0), "r"(w1), "r"(w2), "r"(w3)
                                 : "memory");
                }
                asm volatile("cp.async.wait_all;" ::: "memory");
                __syncthreads();
                compute(sb, ki);
                __syncthreads();
            }
            done = reduce_vote();
            if (done) break;
        }
    }

    // write: each 4-lane group holds maxes for rows wt*16 + h*8 + (lane>>2)
    if ((lane & 3) == 0) {
        const int g = lane >> 2;
#pragma unroll
        for (int mi = 0; mi < NM; mi++)
#pragma unroll
            for (int h = 0; h < 2; h++) {
                int row = wt * 16 + h * 8 + g;
                out[(size_t)(b * TT + t0 + row) * MPP + (m0 + mi)] =
                    tanhf(runmax[mi][h]);
            }
    }
}

// ---------------------------------------------------------------------------
// Launch: inputs: reps_lt[B,T,D] f32, reps_rt[B,T,D] f32, kernel[1,1,1,MP,D] f32.
// Output [B,T,MP] f32.
// ---------------------------------------------------------------------------
extern "C" void kernel_launch(void* const* d_in, const int* in_sizes, int n_in,
                              void* d_out, int out_size) {
    const float* lt = (const float*)d_in[0];
    const float* rt = (const float*)d_in[1];
    const float* kw = (const float*)d_in[2];
    float* out = (float*)d_out;

    cvt_kernel<<<NCVT / 256, 256>>>(lt, rt);

    cudaFuncSetAttribute(match_kernel,
                         cudaFuncAttributeMaxDynamicSharedMemorySize, S_TOTAL);
    dim3 grid(TT / TM, MPP / NM, BB);  // (4, 4, 32) = 512 CTAs
    match_kernel<<<grid, NTHR, S_TOTAL>>>(kw, rt, out);
}

// round 17
// speedup vs baseline: 1.0051x; 1.0051x over previous
#include <cuda_runtime.h>
#include <cuda_fp16.h>
#include <cstdint>

// Problem constants
#define BB  32
#define TT  256
#define DD  512
#define MPP 20

constexpr int TM     = 64;             // CTA t rows
constexpr int TN     = 32;             // s cols per verified chunk
constexpr int NCHK   = TT / TN;        // 8 s-chunks
constexpr int NM     = 4;              // m-planes per CTA (20 = 5 groups of 4)
constexpr int NMW    = 2;              // m-planes per warp (2 m-half warps)
constexpr int KC     = 64;             // k per pipeline stage (4 x k16)
constexpr int NST    = DD / KC;        // 8 stages
constexpr int STAGES = 2;              // buffer ring depth (produce-ahead 1)
constexpr int NTHR   = 256;            // 8 warps: 4 t-subtiles x 2 m-halves
constexpr int OCC    = 3;              // 3 CTAs/SM (85-reg cap) -> 24 warps/SM
constexpr int ROWB   = 144;            // smem row bytes: 128B data + 16B pad
constexpr int A_BYTES   = TM * ROWB;              // 9216
constexpr int B_BYTES   = TN * ROWB;              // 4608
constexpr int STG_BYTES = A_BYTES + B_BYTES;      // 13824

constexpr int S_KMS  = 0;              // 4*512 halves = 4096 B
constexpr int S_MBAR = 4096;           // 4 x 8B mbarriers (2 full + 2 empty)
constexpr int S_BUF  = 4224;           // 128B aligned
constexpr int S_TOTAL = S_BUF + STAGES * STG_BYTES;  // 31872 B (x3 CTAs = 96KB)

constexpr float THRESH = 10.0f;        // tanh(10) = 1 - 4.1e-9; monotone-safe exit

// static device scratch (allocation-free per harness rules)
__device__ __half g_lt[BB * TT * DD];
__device__ __half g_rt0[BB * TN * DD];   // only s-chunk 0 of rt, pre-converted

static __device__ __forceinline__ uint32_t s2u(const void* p) {
    return (uint32_t)__cvta_generic_to_shared(p);
}

#define CP16(dst, src) \
    asm volatile("cp.async.cg.shared.global [%0], [%1], 16;" :: "r"(dst), "l"(src))

#define LDSM4(r0, r1, r2, r3, addr)                                              \
    asm volatile("ldmatrix.sync.aligned.m8n8.x4.shared.b16 {%0,%1,%2,%3}, [%4];" \
                 : "=r"(r0), "=r"(r1), "=r"(r2), "=r"(r3) : "r"(addr))

#define MMA16816(d0, d1, a0, a1, a2, a3, b0, b1)                                  \
    asm volatile("mma.sync.aligned.m16n8k16.row.col.f16.f16.f16.f16 "             \
                 "{%0,%1},{%2,%3,%4,%5},{%6,%7},{%0,%1};"                         \
                 : "+r"(d0), "+r"(d1)                                             \
                 : "r"(a0), "r"(a1), "r"(a2), "r"(a3), "r"(b0), "r"(b1))

// spin (with suspend hint) until the mbarrier phase with given parity completes
#define MBWAIT(addr, ph)                                                          \
    asm volatile("{\n\t.reg .pred P;\n\t"                                         \
                 "MBW%=:\n\t"                                                     \
                 "mbarrier.try_wait.parity.shared.b64 P, [%0], %1, 0x989680;\n\t" \
                 "@!P bra MBW%=;\n\t}"                                            \
                 :: "r"(addr), "r"(ph) : "memory")

static __device__ __forceinline__ uint32_t hmul2u(uint32_t a, uint32_t b) {
    __half2 r = __hmul2(*reinterpret_cast<__half2*>(&a),
                        *reinterpret_cast<__half2*>(&b));
    return *reinterpret_cast<uint32_t*>(&r);
}
static __device__ __forceinline__ uint32_t f2h2(float lo, float hi) {
    __half2 h = __floats2half2_rn(lo, hi);
    return *reinterpret_cast<uint32_t*>(&h);
}

// ---------------------------------------------------------------------------
// Kernel 1: convert lt (all) + rt s-chunk-0 rows to fp16.
// ---------------------------------------------------------------------------
constexpr int NLT  = BB * TT * DD / 16;   // 262144
constexpr int NRT0 = BB * TN * DD / 16;   // 32768
constexpr int NCVT = NLT + NRT0;          // 294912

__global__ void cvt_kernel(const float* __restrict__ lt, const float* __restrict__ rt) {
    int i = blockIdx.x * blockDim.x + threadIdx.x;
    const float4* src;
    __half* dst;
    if (i < NLT) {
        src = reinterpret_cast<const float4*>(lt) + (size_t)i * 4;
        dst = g_lt + (size_t)i * 16;
    } else {
        int j = i - NLT;                       // unit within rt chunk-0 view
        int per_b = TN * DD / 16;              // 1024 units per b
        int b = j / per_b, r = j % per_b;      // rows 0..31 contiguous per b
        src = reinterpret_cast<const float4*>(rt + (size_t)b * TT * DD) + (size_t)r * 4;
        dst = g_rt0 + ((size_t)b * TN * DD + (size_t)r * 16);
    }
    float4 a[4];
#pragma unroll
    for (int j = 0; j < 4; j++) a[j] = src[j];
    uint32_t w[8];
#pragma unroll
    for (int j = 0; j < 4; j++) {
        w[j * 2]     = f2h2(a[j].x, a[j].y);
        w[j * 2 + 1] = f2h2(a[j].z, a[j].w);
    }
    uint4* d = reinterpret_cast<uint4*>(dst);
    d[0] = make_uint4(w[0], w[1], w[2], w[3]);
    d[1] = make_uint4(w[4], w[5], w[6], w[7]);
}

// ---------------------------------------------------------------------------
// Kernel 2: one CTA = (b, t-tile 64, 4 m-planes), 256 threads = 8 warps
// (4 t-subtiles x 2 m-halves; both halves read the SAME A/B SMEM tiles,
// km applied in registers). Grid 640 CTAs x 8 warps = 34.6 warps/SM offered;
// 3 CTAs/SM resident -> 24 warps/SM (latency hiding, was 13.8).
// s-chunk 0 pipelined via mbarrier cp.async; monotone-safe early exit;
// rare exact fallback over chunks 1..7 (B from f32 rt, identical rounding).
// ---------------------------------------------------------------------------
__global__ __launch_bounds__(NTHR, OCC)
void match_kernel(const float* __restrict__ kw, const float* __restrict__ rtf,
                  float* __restrict__ out) {
    extern __shared__ __align__(128) char smem[];
    const int tid = threadIdx.x;
    const int b   = blockIdx.z;
    const int m0  = blockIdx.y * NM;
    const int t0  = blockIdx.x * TM;
    const uint32_t sbase   = s2u(smem);
    const uint32_t sbuf    = sbase + S_BUF;
    const uint32_t mbfull  = sbase + S_MBAR;        // 2 x 8B
    const uint32_t mbempty = sbase + S_MBAR + 16;   // 2 x 8B

    if (tid == 0) {
#pragma unroll
        for (int i = 0; i < STAGES; i++) {
            asm volatile("mbarrier.init.shared.b64 [%0], %1;"
                         :: "r"(mbfull + 8 * i), "r"((uint32_t)NTHR) : "memory");
            asm volatile("mbarrier.init.shared.b64 [%0], %1;"
                         :: "r"(mbempty + 8 * i), "r"(8u) : "memory");
        }
    }

    // stage km rows (m0..m0+3) as fp16
    __half* kms = reinterpret_cast<__half*>(smem + S_KMS);
#pragma unroll
    for (int e = tid; e < NM * DD; e += NTHR) {
        int mi = e >> 9, c = e & (DD - 1);
        kms[e] = __float2half_rn(kw[(m0 + mi) * DD + c]);
    }
    __syncthreads();   // mbarrier init + kms visible

    const __half* ltb  = g_lt  + (size_t)(b * TT + t0) * DD;
    const __half* rt0b = g_rt0 + (size_t)b * TN * DD;
    const float*  rtfb = rtf   + (size_t)b * TT * DD;

    const int wid  = tid >> 5;
    const int lane = tid & 31;
    const int wt   = wid & 3;     // t sub-tile (16 rows)
    const int mh   = wid >> 2;    // m-half (2 m-planes each)

    const uint32_t aoff = (uint32_t)(wt * 16 + (lane & 15)) * ROWB + (lane >> 4) * 16;
    const uint32_t boff = (uint32_t)((lane & 7) + ((lane >> 4) << 3)) * ROWB
                        + ((lane >> 3) & 1) * 16;
    const int c0 = (lane & 3) * 2;

    float runmax[NMW][2];
#pragma unroll
    for (int mi = 0; mi < NMW; mi++) { runmax[mi][0] = -3.4e38f; runmax[mi][1] = -3.4e38f; }

    int fullp[STAGES]  = {0, 0};
    int emptyp[STAGES] = {1, 1};

    auto issueA = [&](uint32_t sb, int st) {
        const int k0 = st * KC;
#pragma unroll
        for (int i = 0; i < 2; i++) {   // A: 64 rows x 8 x 16B = 512 chunks
            int c = tid + i * NTHR, row = c >> 3, sub = c & 7;
            CP16(sb + row * ROWB + sub * 16, ltb + row * DD + k0 + sub * 8);
        }
    };

    auto produce = [&](int st) {        // chunk-0 producer (B from g_rt0)
        const int bfi = st & 1;
        const uint32_t sb = sbuf + bfi * STG_BYTES;
        MBWAIT(mbempty + 8 * bfi, emptyp[bfi]);
        emptyp[bfi] ^= 1;
        issueA(sb, st);
        {   // B: 32 rows x 8 x 16B = 256 chunks (1 per thread)
            int row = tid >> 3, sub = tid & 7;
            CP16(sb + A_BYTES + row * ROWB + sub * 16,
                 rt0b + row * DD + st * KC + sub * 8);
        }
        asm volatile("cp.async.mbarrier.arrive.noinc.shared.b64 [%0];"
                     :: "r"(mbfull + 8 * bfi) : "memory");
    };

    auto ldfrag = [&](uint32_t sb, int kk, uint32_t* bf, uint32_t* af) {
        LDSM4(bf[0], bf[1], bf[2], bf[3], sb + A_BYTES + boff + kk * 32);
        LDSM4(bf[4], bf[5], bf[6], bf[7], sb + A_BYTES + boff + 16 * ROWB + kk * 32);
        LDSM4(af[0], af[1], af[2], af[3], sb + aoff + kk * 32);
    };

    uint32_t acc[NMW][4][2];
    auto clear_acc = [&]() {
#pragma unroll
        for (int mi = 0; mi < NMW; mi++)
#pragma unroll
            for (int ni = 0; ni < 4; ni++) { acc[mi][ni][0] = 0u; acc[mi][ni][1] = 0u; }
    };

    auto compute = [&](uint32_t sb, int ki) {
        uint32_t bfA[8], afA[4], bfB[8], afB[4];
        ldfrag(sb, 0, bfA, afA);
#pragma unroll
        for (int kk = 0; kk < 4; kk++) {
            uint32_t* bf = (kk & 1) ? bfB : bfA;
            uint32_t* af = (kk & 1) ? afB : afA;
            if (kk < 3) ldfrag(sb, kk + 1, (kk & 1) ? bfA : bfB, (kk & 1) ? afA : afB);
            const int kb = ki * KC + kk * 16;
#pragma unroll
            for (int mi = 0; mi < NMW; mi++) {
                const int mrow = mh * NMW + mi;
                const uint32_t kp0 =
                    *reinterpret_cast<const uint32_t*>(&kms[mrow * DD + kb + c0]);
                const uint32_t kp1 =
                    *reinterpret_cast<const uint32_t*>(&kms[mrow * DD + kb + c0 + 8]);
                uint32_t a0 = hmul2u(af[0], kp0);
                uint32_t a1 = hmul2u(af[1], kp0);
                uint32_t a2 = hmul2u(af[2], kp1);
                uint32_t a3 = hmul2u(af[3], kp1);
#pragma unroll
                for (int ni = 0; ni < 4; ni++)
                    MMA16816(acc[mi][ni][0], acc[mi][ni][1],
                             a0, a1, a2, a3, bf[ni * 2], bf[ni * 2 + 1]);
            }
        }
    };

    // returns true if every row's running max clears THRESH (monotone-safe)
    auto reduce_vote = [&]() -> int {
        bool pred = true;
#pragma unroll
        for (int mi = 0; mi < NMW; mi++)
#pragma unroll
            for (int h = 0; h < 2; h++) {
                __half2 v = *reinterpret_cast<__half2*>(&acc[mi][0][h]);
#pragma unroll
                for (int ni = 1; ni < 4; ni++)
                    v = __hmax2(v, *reinterpret_cast<__half2*>(&acc[mi][ni][h]));
                float fm = fmaxf(__low2float(v), __high2float(v));
                fm = fmaxf(fm, __shfl_xor_sync(0xffffffffu, fm, 1));
                fm = fmaxf(fm, __shfl_xor_sync(0xffffffffu, fm, 2));
                runmax[mi][h] = fmaxf(runmax[mi][h], fm);
                pred = pred && (runmax[mi][h] > THRESH);
            }
        return __syncthreads_and((int)pred);
    };

    // ---- chunk 0: pipelined fast path (ring of 2, produce-ahead 1) ----
    clear_acc();
    produce(0);
#pragma unroll
    for (int ki = 0; ki < NST; ki++) {
        const int bfi = ki & 1;
        MBWAIT(mbfull + 8 * bfi, fullp[bfi]);
        fullp[bfi] ^= 1;
        if (ki + 1 < NST) produce(ki + 1);
        compute(sbuf + bfi * STG_BYTES, ki);
        __syncwarp();
        if (lane == 0) {
            asm volatile("{\n\t.reg .b64 t;\n\t"
                         "mbarrier.arrive.shared.b64 t, [%0];\n\t}"
                         :: "r"(mbempty + 8 * bfi) : "memory");
        }
    }
    int done = reduce_vote();

    // ---- chunks 1..7: rare exact fallback (B from f32 rt, converted here) ----
    if (!done) {
        for (int chunk = 1; chunk < NCHK; chunk++) {
            clear_acc();
            for (int ki = 0; ki < NST; ki++) {
                const uint32_t sb = sbuf + (ki & 1) * STG_BYTES;
                issueA(sb, ki);
                asm volatile("cp.async.commit_group;" ::: "memory");
                {   // B: f32 -> f16 in regs -> STS (1 chunk per thread)
                    int row = tid >> 3, sub = tid & 7;
                    const float* s = rtfb + (size_t)(chunk * TN + row) * DD
                                   + ki * KC + sub * 8;
                    float4 f0 = *reinterpret_cast<const float4*>(s);
                    float4 f1 = *reinterpret_cast<const float4*>(s + 4);
                    uint32_t w0 = f2h2(f0.x, f0.y), w1 = f2h2(f0.z, f0.w);
                    uint32_t w2 = f2h2(f1.x, f1.y), w3 = f2h2(f1.z, f1.w);
                    uint32_t dstp = sb + A_BYTES + row * ROWB + sub * 16;
                    asm volatile("st.shared.v4.b32 [%0], {%1,%2,%3,%4};"
                                 :: "r"(dstp), "r"(w0), "r"(w1), "r"(w2), "r"(w3)
                                 : "memory");
                }
                asm volatile("cp.async.wait_all;" ::: "memory");
                __syncthreads();
                compute(sb, ki);
                __syncthreads();
            }
            done = reduce_vote();
            if (done) break;
        }
    }

    // write: each 4-lane group holds maxes for rows wt*16 + h*8 + (lane>>2)
    if ((lane & 3) == 0) {
        const int g = lane >> 2;
#pragma unroll
        for (int mi = 0; mi < NMW; mi++)
#pragma unroll
            for (int h = 0; h < 2; h++) {
                int row = wt * 16 + h * 8 + g;
                out[(size_t)(b * TT + t0 + row) * MPP + (m0 + mh * NMW + mi)] =
                    tanhf(runmax[mi][h]);
            }
    }
}

// ---------------------------------------------------------------------------
// Launch: inputs: reps_lt[B,T,D] f32, reps_rt[B,T,D] f32, kernel[1,1,1,MP,D] f32.
// Output [B,T,MP] f32.
// ---------------------------------------------------------------------------
extern "C" void kernel_launch(void* const* d_in, const int* in_sizes, int n_in,
                              void* d_out, int out_size) {
    const float* lt = (const float*)d_in[0];
    const float* rt = (const float*)d_in[1];
    const float* kw = (const float*)d_in[2];
    float* out = (float*)d_out;

    cvt_kernel<<<NCVT / 256, 256>>>(lt, rt);

    cudaFuncSetAttribute(match_kernel,
                         cudaFuncAttributeMaxDynamicSharedMemorySize, S_TOTAL);
    dim3 grid(TT / TM, MPP / NM, BB);  // (4, 5, 32) = 640 CTAs
    match_kernel<<<grid, NTHR, S_TOTAL>>>(kw, rt, out);
}